// round 1
// baseline (speedup 1.0000x reference)
#include <cuda_runtime.h>
#include <math.h>

#define NFFT  4096
#define LOGN  12
#define LSEQ  2048
#define BB    32
#define DD    32
#define KK    32
#define OO    32
#define JH    48      // truncated impulse-response length of y-recurrence
#define NHALF 2049    // frequency bins 0..N/2 (Hermitian half)
#define TFIX  64      // first TFIX timesteps recomputed exactly

// ---------------- scratch (device globals; no allocation allowed) ------------
__device__ float2 g_U[BB][DD][NFFT];     // FFT of inputs      (b, d, f)
__device__ float2 g_G[BB][OO][NFFT];     // output spectra     (b, o, f)
__device__ float2 g_W[NFFT][DD][OO];     // combined filter    (f, d, o)
__device__ float2 g_V[KK][NFFT];         // FFT of eig_vecs    (k, f)
__device__ float2 g_Hh[NHALF][OO][OO];   // DFT of h           (f, o, o')
__device__ float  g_h[JH][OO][OO];       // impulse response of recurrence
__device__ float  g_Fs[TFIX][DD][OO];    // time-domain F for the fixup region

// ---------------- helpers ----------------------------------------------------
__device__ __forceinline__ float2 cmulf(float2 a, float2 b) {
    return make_float2(a.x*b.x - a.y*b.y, a.x*b.y + a.y*b.x);
}

// In-place radix-2 Cooley-Tukey FFT over 4096 complex values in shared memory.
// sign = -1 forward (numpy convention), +1 inverse (caller scales by 1/N).
// Call with blockDim.x = 1024.
__device__ void fft_shared(float2* x, float sign) {
    int tid = threadIdx.x;
    __syncthreads();
    // bit-reversal permutation
    for (int i = tid; i < NFFT; i += 1024) {
        int j = (int)(__brev((unsigned)i) >> (32 - LOGN));
        if (i < j) { float2 t = x[i]; x[i] = x[j]; x[j] = t; }
    }
    __syncthreads();
    int shift = 0;
    for (int len = 2; len <= NFFT; len <<= 1, shift++) {
        int half = len >> 1;
        float ang0 = sign * 6.283185307179586f / (float)len;
        for (int bt = tid; bt < NFFT / 2; bt += 1024) {
            int p  = bt & (half - 1);
            int g  = bt >> shift;
            int i0 = (g << (shift + 1)) + p;
            int i1 = i0 + half;
            float s, c;
            sincosf(ang0 * (float)p, &s, &c);
            float2 w = make_float2(c, s);
            float2 u = x[i0];
            float2 v = x[i1];
            float2 t = cmulf(v, w);
            x[i0] = make_float2(u.x + t.x, u.y + t.y);
            x[i1] = make_float2(u.x - t.x, u.y - t.y);
        }
        __syncthreads();
    }
}

// ---------------- kernel 1: impulse response of y-recurrence -----------------
// h0 = I, h1 = M1, h_j = M1 h_{j-1} + M2 h_{j-2}
__global__ void k_h(const float* __restrict__ m_y) {
    __shared__ float M1[OO * OO], M2[OO * OO], hp[OO * OO], hp2[OO * OO];
    int tid = threadIdx.x;                  // 1024
    int o = tid >> 5, i = tid & 31;
    M1[o * 32 + i] = m_y[o * 64 + i];
    M2[o * 32 + i] = m_y[o * 64 + 32 + i];
    float h0 = (o == i) ? 1.f : 0.f;
    hp2[o * 32 + i] = h0;
    g_h[0][o][i] = h0;
    hp[o * 32 + i] = m_y[o * 64 + i];
    g_h[1][o][i] = m_y[o * 64 + i];
    __syncthreads();
    for (int j = 2; j < JH; j++) {
        float acc = 0.f;
        #pragma unroll
        for (int t = 0; t < 32; t++)
            acc += M1[o * 32 + t] * hp[t * 32 + i] + M2[o * 32 + t] * hp2[t * 32 + i];
        __syncthreads();
        hp2[o * 32 + i] = hp[o * 32 + i];
        __syncthreads();
        hp[o * 32 + i] = acc;
        g_h[j][o][i] = acc;
        __syncthreads();
    }
}

// ---------------- kernel 2: direct DFT of h (half spectrum) ------------------
__global__ void k_hhat() {
    int f = blockIdx.x;                     // 0..2048
    int tid = threadIdx.x;                  // 1024
    int o = tid >> 5, i = tid & 31;
    float ang = -6.283185307179586f * (float)f / (float)NFFT;
    float s, c;
    sincosf(ang, &s, &c);
    float2 w   = make_float2(c, s);
    float2 cur = make_float2(1.f, 0.f);
    float2 acc = make_float2(0.f, 0.f);
    for (int j = 0; j < JH; j++) {
        float hv = g_h[j][o][i];
        acc.x += hv * cur.x;
        acc.y += hv * cur.y;
        cur = cmulf(cur, w);
    }
    g_Hh[f][o][i] = acc;
}

// ---------------- kernel 3: FFT of eig_vecs (pack column pairs) --------------
__global__ void k_fft_v(const float* __restrict__ ev) {
    __shared__ float2 sh[NFFT];
    int kp = blockIdx.x;                    // 0..15 -> filters 2kp, 2kp+1
    int tid = threadIdx.x;                  // 1024
    for (int t = tid; t < LSEQ; t += 1024) {
        const float2 v = *reinterpret_cast<const float2*>(ev + (size_t)t * KK + 2 * kp);
        sh[t] = v;
    }
    for (int t = LSEQ + tid; t < NFFT; t += 1024) sh[t] = make_float2(0.f, 0.f);
    fft_shared(sh, -1.f);
    for (int f = tid; f < NFFT; f += 1024) {
        float2 zf = sh[f];
        float2 zm = sh[(NFFT - f) & (NFFT - 1)];
        g_V[2 * kp][f]     = make_float2(0.5f * (zf.x + zm.x), 0.5f * (zf.y - zm.y));
        g_V[2 * kp + 1][f] = make_float2(0.5f * (zf.y + zm.y), 0.5f * (zm.x - zf.x));
    }
}

// ---------------- kernel 4: build combined filter W --------------------------
// FA[f,d,o'] = sum_k (lam_k^.25 V[f,k]) m_phi[k*D+d, o']  +  sum_j m_u[o',d,j] e^{-i 2pi f j/N}
// W[f,d,o]   = sum_{o'} FA[f,d,o'] * Hhat[f,o,o'],  mirrored Hermitianly to upper bins
__global__ void k_W(const float* __restrict__ eig_vals,
                    const float* __restrict__ m_phi,
                    const float* __restrict__ m_u) {
    __shared__ float2 sv[KK];
    __shared__ float2 FA[DD * OO];
    __shared__ float2 Hs[OO * 33];
    int f = blockIdx.x;                     // 0..2048
    int tid = threadIdx.x;                  // 1024
    int d = tid >> 5, q = tid & 31;
    if (tid < KK) {
        float sc = sqrtf(sqrtf(eig_vals[tid]));
        float2 v = g_V[tid][f];
        sv[tid] = make_float2(v.x * sc, v.y * sc);
    }
    __syncthreads();
    float2 fa = make_float2(0.f, 0.f);
    #pragma unroll
    for (int k = 0; k < KK; k++) {
        float m = m_phi[(k * DD + d) * OO + q];
        fa.x += sv[k].x * m;
        fa.y += sv[k].y * m;
    }
    float ang = -6.283185307179586f * (float)f / (float)NFFT;
    float s1, c1, s2, c2;
    sincosf(ang, &s1, &c1);
    sincosf(2.f * ang, &s2, &c2);
    float a0 = m_u[(q * DD + d) * 3 + 0];
    float a1 = m_u[(q * DD + d) * 3 + 1];
    float a2 = m_u[(q * DD + d) * 3 + 2];
    fa.x += a0 + a1 * c1 + a2 * c2;
    fa.y += a1 * s1 + a2 * s2;
    FA[d * OO + q] = fa;
    Hs[d * 33 + q] = g_Hh[f][d][q];         // (d,q) spans all (o,o')
    __syncthreads();
    float2 acc = make_float2(0.f, 0.f);
    #pragma unroll
    for (int t = 0; t < OO; t++) {
        float2 a = FA[d * OO + t];
        float2 h = Hs[q * 33 + t];
        acc.x += a.x * h.x - a.y * h.y;
        acc.y += a.x * h.y + a.y * h.x;
    }
    g_W[f][d][q] = acc;
    if (f != 0 && f != NFFT / 2)
        g_W[NFFT - f][d][q] = make_float2(acc.x, -acc.y);
}

// ---------------- kernel 5: FFT of inputs (pack channel pairs) ---------------
__global__ void k_fft_fwd(const float* __restrict__ inp) {
    __shared__ float2 sh[NFFT];
    int blk = blockIdx.x;                   // 512: (b, dpair)
    int b = blk >> 4, dp = blk & 15;
    int tid = threadIdx.x;                  // 1024
    for (int t = tid; t < LSEQ; t += 1024) {
        const float2 v = *reinterpret_cast<const float2*>(
            inp + ((size_t)(b * LSEQ + t)) * DD + 2 * dp);
        sh[t] = v;
    }
    for (int t = LSEQ + tid; t < NFFT; t += 1024) sh[t] = make_float2(0.f, 0.f);
    fft_shared(sh, -1.f);
    for (int f = tid; f < NFFT; f += 1024) {
        float2 zf = sh[f];
        float2 zm = sh[(NFFT - f) & (NFFT - 1)];
        g_U[b][2 * dp][f]     = make_float2(0.5f * (zf.x + zm.x), 0.5f * (zf.y - zm.y));
        g_U[b][2 * dp + 1][f] = make_float2(0.5f * (zf.y + zm.y), 0.5f * (zm.x - zf.x));
    }
}

// ---------------- kernel 6: per-bin complex matvec G = U * W -----------------
__global__ void k_mul() {
    __shared__ float2 Ws[4 * DD * OO];      // 32 KB
    __shared__ float2 Us[DD * 4];
    int f0 = blockIdx.x * 4;
    int tid = threadIdx.x;                  // 128
    const float2* wsrc = &g_W[f0][0][0];
    for (int idx = tid; idx < 4 * DD * OO; idx += 128) Ws[idx] = wsrc[idx];
    __syncthreads();
    int fi = tid & 3, o = tid >> 2;
    float2 Wr[DD];
    #pragma unroll
    for (int d = 0; d < DD; d++) Wr[d] = Ws[fi * DD * OO + d * OO + o];
    int dl = tid >> 2, fl = tid & 3;
    for (int b = 0; b < BB; b++) {
        Us[dl * 4 + fl] = g_U[b][dl][f0 + fl];
        __syncthreads();
        float2 acc = make_float2(0.f, 0.f);
        #pragma unroll
        for (int d = 0; d < DD; d++) {
            float2 u = Us[d * 4 + fi];
            float2 w = Wr[d];
            acc.x += u.x * w.x - u.y * w.y;
            acc.y += u.x * w.y + u.y * w.x;
        }
        g_G[b][o][f0 + fi] = acc;
        __syncthreads();
    }
}

// ---------------- kernel 7: inverse FFT (pack output-channel pairs) ----------
__global__ void k_ifft(float* __restrict__ out) {
    __shared__ float2 sh[NFFT];
    int blk = blockIdx.x;                   // 512: (b, opair)
    int b = blk >> 4, op = blk & 15;
    int tid = threadIdx.x;                  // 1024
    for (int f = tid; f < NFFT; f += 1024) {
        float2 a = g_G[b][2 * op][f];
        float2 c = g_G[b][2 * op + 1][f];
        sh[f] = make_float2(a.x - c.y, a.y + c.x);
    }
    fft_shared(sh, 1.f);
    const float inv = 1.f / (float)NFFT;
    for (int t = tid; t < LSEQ; t += 1024) {
        float2 z = sh[t];
        float2* p = reinterpret_cast<float2*>(out + ((size_t)(b * LSEQ + t)) * OO + 2 * op);
        *p = make_float2(z.x * inv, z.y * inv);
    }
}

// ---------------- kernel 8: time-domain F for the fixup region ---------------
__global__ void k_Fs(const float* __restrict__ eig_vals,
                     const float* __restrict__ ev,
                     const float* __restrict__ m_phi) {
    __shared__ float sc[KK];
    __shared__ float vv[KK];
    int s = blockIdx.x;                     // 0..63
    int tid = threadIdx.x;                  // 1024
    if (tid < KK) {
        sc[tid] = sqrtf(sqrtf(eig_vals[tid]));
        vv[tid] = ev[(size_t)s * KK + tid];
    }
    __syncthreads();
    int d = tid >> 5, o = tid & 31;
    float acc = 0.f;
    #pragma unroll
    for (int k = 0; k < KK; k++)
        acc += sc[k] * vv[k] * m_phi[(k * DD + d) * OO + o];
    g_Fs[s][d][o] = acc;
}

// ---------------- kernel 9: exact recompute of y for t < TFIX ----------------
__global__ void k_fix(const float* __restrict__ inp,
                      const float* __restrict__ m_u,
                      const float* __restrict__ m_y,
                      float* __restrict__ out) {
    __shared__ float u[TFIX * DD];
    __shared__ float Fsh[DD * OO];
    __shared__ float delta[TFIX * OO];
    __shared__ float y1[OO], y2[OO];
    int b = blockIdx.x, tid = threadIdx.x;  // 256
    for (int idx = tid; idx < TFIX * DD; idx += 256)
        u[idx] = inp[(size_t)b * LSEQ * DD + idx];
    __syncthreads();
    float acc[8];
    #pragma unroll
    for (int r = 0; r < 8; r++) {
        int idx = tid + r * 256;
        int t = idx >> 5, o = idx & 31;
        float a = 0.f;
        for (int j = 0; j < 3; j++) {
            if (t >= j) {
                #pragma unroll
                for (int i = 0; i < DD; i++)
                    a += m_u[(o * DD + i) * 3 + j] * u[(t - j) * DD + i];
            }
        }
        acc[r] = a;
    }
    for (int s = 0; s < TFIX; s++) {
        const float* fp = &g_Fs[s][0][0];
        for (int idx = tid; idx < DD * OO; idx += 256) Fsh[idx] = fp[idx];
        __syncthreads();
        #pragma unroll
        for (int r = 0; r < 8; r++) {
            int idx = tid + r * 256;
            int t = idx >> 5, o = idx & 31;
            if (t >= s) {
                float a = acc[r];
                const float* ur = &u[(t - s) * DD];
                #pragma unroll
                for (int d = 0; d < DD; d++)
                    a += ur[d] * Fsh[d * OO + o];
                acc[r] = a;
            }
        }
        __syncthreads();
    }
    #pragma unroll
    for (int r = 0; r < 8; r++) { int idx = tid + r * 256; delta[idx] = acc[r]; }
    __syncthreads();
    if (tid < OO) {
        int o = tid;
        y1[o] = 0.f; y2[o] = 0.f;
        __syncwarp();
        for (int t = 0; t < TFIX; t++) {
            float a = delta[t * OO + o];
            #pragma unroll
            for (int i = 0; i < OO; i++)
                a += m_y[o * 64 + i] * y1[i] + m_y[o * 64 + 32 + i] * y2[i];
            __syncwarp();
            y2[o] = y1[o];
            __syncwarp();
            y1[o] = a;
            __syncwarp();
            out[((size_t)(b * LSEQ + t)) * OO + o] = a;
        }
    }
}

// ---------------- launch ------------------------------------------------------
extern "C" void kernel_launch(void* const* d_in, const int* in_sizes, int n_in,
                              void* d_out, int out_size) {
    const float* inputs  = (const float*)d_in[0];
    const float* eigvals = (const float*)d_in[1];
    const float* eigvecs = (const float*)d_in[2];
    const float* m_u     = (const float*)d_in[3];
    const float* m_phi   = (const float*)d_in[4];
    const float* m_y     = (const float*)d_in[5];
    float* out = (float*)d_out;

    k_h      <<<1, 1024>>>(m_y);
    k_hhat   <<<NHALF, 1024>>>();
    k_fft_v  <<<KK / 2, 1024>>>(eigvecs);
    k_W      <<<NHALF, 1024>>>(eigvals, m_phi, m_u);
    k_fft_fwd<<<BB * DD / 2, 1024>>>(inputs);
    k_mul    <<<NFFT / 4, 128>>>();
    k_ifft   <<<BB * OO / 2, 1024>>>(out);
    k_Fs     <<<TFIX, 1024>>>(eigvals, eigvecs, m_phi);
    k_fix    <<<BB, 256>>>(inputs, m_u, m_y, out);
}

// round 2
// speedup vs baseline: 1.2503x; 1.2503x over previous
#include <cuda_runtime.h>
#include <math.h>

#define NFFT  4096
#define LOGN  12
#define LSEQ  2048
#define BB    32
#define DD    32
#define KK    32
#define OO    32
#define JH    32      // truncated impulse-response length of y-recurrence
#define FH    2064    // padded half-spectrum bin count (>= 2049, 128B-aligned rows)
#define TFIX  64      // first TFIX timesteps recomputed exactly

// ---------------- scratch (device globals; no allocation allowed) ------------
__device__ float2 g_U[BB][DD][FH];     // FFT of inputs      (b, d, f<=half)
__device__ float2 g_G[BB][OO][FH];     // output spectra     (b, o, f<=half)
__device__ float2 g_W[FH][DD][OO];     // combined filter    (f<=half, d, o)
__device__ float2 g_V[KK][FH];         // FFT of eig_vecs    (k, f<=half)
__device__ float  g_h[JH][OO][OO];     // impulse response of recurrence
__device__ float  g_Fs[TFIX][DD][OO];  // time-domain F for the fixup region
__device__ float2 g_tw[NFFT];          // twiddles, per-stage layout [half + p]

// ---------------- helpers ----------------------------------------------------
__device__ __forceinline__ float2 cmulf(float2 a, float2 b) {
    return make_float2(a.x*b.x - a.y*b.y, a.x*b.y + a.y*b.x);
}

// ---------------- kernel 0: twiddle table ------------------------------------
// stage s (half = 2^s) entries live at [half .. 2*half): w_p = exp(-i pi p / half)
__global__ void k_tw() {
    int i = blockIdx.x * 1024 + threadIdx.x;
    if (i >= NFFT) return;
    if (i == 0) { g_tw[0] = make_float2(1.f, 0.f); return; }
    int s = 31 - __clz(i);
    int half = 1 << s;
    int p = i - half;
    float ang = -3.14159265358979323846f * (float)p / (float)half;
    float sn, cs; sincosf(ang, &sn, &cs);
    g_tw[i] = make_float2(cs, sn);
}

// In-place radix-2 FFT over 4096 complex values in shared memory.
// inverse=0 forward (numpy convention), inverse=1 conjugated twiddles
// (caller scales by 1/N). blockDim.x = 1024.
__device__ void fft_shared(float2* x, int inverse) {
    int tid = threadIdx.x;
    __syncthreads();
    for (int i = tid; i < NFFT; i += 1024) {
        int j = (int)(__brev((unsigned)i) >> (32 - LOGN));
        if (i < j) { float2 t = x[i]; x[i] = x[j]; x[j] = t; }
    }
    __syncthreads();
    for (int s = 0; s < LOGN; s++) {
        int half = 1 << s;
        #pragma unroll
        for (int r = 0; r < 2; r++) {
            int bt = tid + r * 1024;
            int p  = bt & (half - 1);
            int g  = bt >> s;
            int i0 = (g << (s + 1)) + p;
            int i1 = i0 + half;
            float2 w = __ldg(&g_tw[half + p]);
            float wy = inverse ? -w.y : w.y;
            float2 u = x[i0];
            float2 v = x[i1];
            float tx = v.x * w.x - v.y * wy;
            float ty = v.x * wy + v.y * w.x;
            x[i0] = make_float2(u.x + tx, u.y + ty);
            x[i1] = make_float2(u.x - tx, u.y - ty);
        }
        __syncthreads();
    }
}

// ---------------- kernel 1: impulse response of y-recurrence -----------------
__global__ void k_h(const float* __restrict__ m_y) {
    __shared__ float M1[OO * OO], M2[OO * OO], hp[OO * OO], hp2[OO * OO];
    int tid = threadIdx.x;                  // 1024
    int o = tid >> 5, i = tid & 31;
    M1[o * 32 + i] = m_y[o * 64 + i];
    M2[o * 32 + i] = m_y[o * 64 + 32 + i];
    float h0 = (o == i) ? 1.f : 0.f;
    hp2[o * 32 + i] = h0;
    g_h[0][o][i] = h0;
    hp[o * 32 + i] = m_y[o * 64 + i];
    g_h[1][o][i] = m_y[o * 64 + i];
    __syncthreads();
    for (int j = 2; j < JH; j++) {
        float acc = 0.f;
        #pragma unroll
        for (int t = 0; t < 32; t++)
            acc += M1[o * 32 + t] * hp[t * 32 + i] + M2[o * 32 + t] * hp2[t * 32 + i];
        __syncthreads();
        hp2[o * 32 + i] = hp[o * 32 + i];
        __syncthreads();
        hp[o * 32 + i] = acc;
        g_h[j][o][i] = acc;
        __syncthreads();
    }
}

// ---------------- kernel 2: FFT of eig_vecs (pack column pairs) --------------
__global__ void k_fft_v(const float* __restrict__ ev) {
    __shared__ float2 sh[NFFT];
    int kp = blockIdx.x;                    // 0..15 -> filters 2kp, 2kp+1
    int tid = threadIdx.x;                  // 1024
    for (int t = tid; t < LSEQ; t += 1024) {
        const float2 v = *reinterpret_cast<const float2*>(ev + (size_t)t * KK + 2 * kp);
        sh[t] = v;
    }
    for (int t = LSEQ + tid; t < NFFT; t += 1024) sh[t] = make_float2(0.f, 0.f);
    fft_shared(sh, 0);
    for (int f = tid; f < FH; f += 1024) {
        float2 zf = sh[f];
        float2 zm = sh[(NFFT - f) & (NFFT - 1)];
        g_V[2 * kp][f]     = make_float2(0.5f * (zf.x + zm.x), 0.5f * (zf.y - zm.y));
        g_V[2 * kp + 1][f] = make_float2(0.5f * (zf.y + zm.y), 0.5f * (zm.x - zf.x));
    }
}

// ---------------- kernel 3: fused combined filter W (2 bins / block) ---------
// Hhat[f,o,o'] = sum_j h_j[o,o'] e^{-i 2pi f j / N}
// FA[f,d,o']   = sum_k (lam_k^.25 V[f,k]) m_phi[k*D+d,o'] + sum_j m_u[o',d,j] e^{-i 2pi f j/N}
// W[f,d,o]     = sum_{o'} FA[f,d,o'] * Hhat[f,o,o']
__global__ void k_W(const float* __restrict__ eig_vals,
                    const float* __restrict__ m_phi,
                    const float* __restrict__ m_u) {
    __shared__ float2 Hs[2][OO][OO + 1];    // stored transposed: Hs[bin][o'][o]
    __shared__ float2 FAs[2][DD][OO];
    __shared__ float2 sv[2][KK];
    int f0 = blockIdx.x * 2;
    int tid = threadIdx.x;                  // 1024
    int o = tid >> 5, i = tid & 31;

    float s0, c0, s1, c1;
    sincosf(-6.283185307179586f * (float)f0 / (float)NFFT, &s0, &c0);
    sincosf(-6.283185307179586f * (float)(f0 + 1) / (float)NFFT, &s1, &c1);
    float2 w0 = make_float2(c0, s0), w1 = make_float2(c1, s1);

    // Hhat for both bins (thread owns element (o, i))
    float2 acc0 = make_float2(0.f, 0.f), acc1 = acc0;
    float2 cur0 = make_float2(1.f, 0.f), cur1 = cur0;
    #pragma unroll 4
    for (int j = 0; j < JH; j++) {
        float hv = g_h[j][o][i];
        acc0.x += hv * cur0.x; acc0.y += hv * cur0.y;
        acc1.x += hv * cur1.x; acc1.y += hv * cur1.y;
        cur0 = cmulf(cur0, w0);
        cur1 = cmulf(cur1, w1);
    }
    Hs[0][i][o] = acc0;                     // transposed store
    Hs[1][i][o] = acc1;

    if (tid < 64) {
        int bin = tid >> 5, k = tid & 31;
        float sc = sqrtf(sqrtf(eig_vals[k]));
        float2 v = g_V[k][f0 + bin];
        sv[bin][k] = make_float2(v.x * sc, v.y * sc);
    }
    __syncthreads();

    // FA for both bins (thread owns (d=o, q=i))
    int d = o, q = i;
    float2 fa0 = make_float2(0.f, 0.f), fa1 = fa0;
    #pragma unroll 8
    for (int k = 0; k < KK; k++) {
        float m = m_phi[(k * DD + d) * OO + q];
        fa0.x += sv[0][k].x * m; fa0.y += sv[0][k].y * m;
        fa1.x += sv[1][k].x * m; fa1.y += sv[1][k].y * m;
    }
    float a0 = m_u[(q * DD + d) * 3 + 0];
    float a1 = m_u[(q * DD + d) * 3 + 1];
    float a2 = m_u[(q * DD + d) * 3 + 2];
    {   // bin 0: e^{-i t0} = w0, e^{-2i t0} from double angle
        float c2 = w0.x * w0.x - w0.y * w0.y, sn2 = 2.f * w0.x * w0.y;
        fa0.x += a0 + a1 * w0.x + a2 * c2;
        fa0.y += a1 * w0.y + a2 * sn2;
    }
    {   // bin 1
        float c2 = w1.x * w1.x - w1.y * w1.y, sn2 = 2.f * w1.x * w1.y;
        fa1.x += a0 + a1 * w1.x + a2 * c2;
        fa1.y += a1 * w1.y + a2 * sn2;
    }
    FAs[0][d][q] = fa0;
    FAs[1][d][q] = fa1;
    __syncthreads();

    // W[d, o] = sum_t FA[d, t] * Hhat[o, t]   (Hs holds Hhat^T: Hs[t][o])
    float2 r0 = make_float2(0.f, 0.f), r1 = r0;
    #pragma unroll 8
    for (int t = 0; t < OO; t++) {
        float2 A = FAs[0][d][t];
        float2 h = Hs[0][t][i];
        r0.x += A.x * h.x - A.y * h.y;
        r0.y += A.x * h.y + A.y * h.x;
        float2 B = FAs[1][d][t];
        float2 g = Hs[1][t][i];
        r1.x += B.x * g.x - B.y * g.y;
        r1.y += B.x * g.y + B.y * g.x;
    }
    g_W[f0][d][i]     = r0;
    g_W[f0 + 1][d][i] = r1;
}

// ---------------- kernel 4: FFT of inputs (pack channel pairs) ---------------
__global__ void k_fft_fwd(const float* __restrict__ inp) {
    __shared__ float2 sh[NFFT];
    int blk = blockIdx.x;                   // 512: (b, dpair)
    int b = blk >> 4, dp = blk & 15;
    int tid = threadIdx.x;                  // 1024
    for (int t = tid; t < LSEQ; t += 1024) {
        const float2 v = *reinterpret_cast<const float2*>(
            inp + ((size_t)(b * LSEQ + t)) * DD + 2 * dp);
        sh[t] = v;
    }
    for (int t = LSEQ + tid; t < NFFT; t += 1024) sh[t] = make_float2(0.f, 0.f);
    fft_shared(sh, 0);
    for (int f = tid; f < FH; f += 1024) {
        float2 zf = sh[f];
        float2 zm = sh[(NFFT - f) & (NFFT - 1)];
        g_U[b][2 * dp][f]     = make_float2(0.5f * (zf.x + zm.x), 0.5f * (zf.y - zm.y));
        g_U[b][2 * dp + 1][f] = make_float2(0.5f * (zf.y + zm.y), 0.5f * (zm.x - zf.x));
    }
}

// ---------------- kernel 5: per-bin complex matvec G = U * W (half spectrum) -
__global__ void k_mul() {
    __shared__ float2 Ws[4 * DD * OO];      // 32 KB
    __shared__ float2 Us[DD * 4];
    int f0 = blockIdx.x * 4;
    int tid = threadIdx.x;                  // 128
    const float2* wsrc = &g_W[f0][0][0];
    for (int idx = tid; idx < 4 * DD * OO; idx += 128) Ws[idx] = wsrc[idx];
    __syncthreads();
    int fi = tid & 3, o = tid >> 2;
    float2 Wr[DD];
    #pragma unroll
    for (int d = 0; d < DD; d++) Wr[d] = Ws[fi * DD * OO + d * OO + o];
    int dl = tid >> 2, fl = tid & 3;
    for (int b = 0; b < BB; b++) {
        Us[dl * 4 + fl] = g_U[b][dl][f0 + fl];
        __syncthreads();
        float2 acc = make_float2(0.f, 0.f);
        #pragma unroll
        for (int d = 0; d < DD; d++) {
            float2 u = Us[d * 4 + fi];
            float2 w = Wr[d];
            acc.x += u.x * w.x - u.y * w.y;
            acc.y += u.x * w.y + u.y * w.x;
        }
        g_G[b][o][f0 + fi] = acc;
        __syncthreads();
    }
}

// ---------------- kernel 6: inverse FFT (Hermitian reconstruct + pack) -------
__global__ void k_ifft(float* __restrict__ out) {
    __shared__ float2 sh[NFFT];
    int blk = blockIdx.x;                   // 512: (b, opair)
    int b = blk >> 4, op = blk & 15;
    int tid = threadIdx.x;                  // 1024
    for (int f = tid; f < NFFT; f += 1024) {
        int mir = f > NFFT / 2;
        int fm = mir ? NFFT - f : f;
        float sgn = mir ? -1.f : 1.f;
        float2 a = g_G[b][2 * op][fm];
        float2 c = g_G[b][2 * op + 1][fm];
        a.y *= sgn; c.y *= sgn;
        sh[f] = make_float2(a.x - c.y, a.y + c.x);
    }
    fft_shared(sh, 1);
    const float inv = 1.f / (float)NFFT;
    for (int t = tid; t < LSEQ; t += 1024) {
        float2 z = sh[t];
        float2* p = reinterpret_cast<float2*>(out + ((size_t)(b * LSEQ + t)) * OO + 2 * op);
        *p = make_float2(z.x * inv, z.y * inv);
    }
}

// ---------------- kernel 7: time-domain F for the fixup region ---------------
__global__ void k_Fs(const float* __restrict__ eig_vals,
                     const float* __restrict__ ev,
                     const float* __restrict__ m_phi) {
    __shared__ float sc[KK];
    __shared__ float vv[KK];
    int s = blockIdx.x;                     // 0..63
    int tid = threadIdx.x;                  // 1024
    if (tid < KK) {
        sc[tid] = sqrtf(sqrtf(eig_vals[tid]));
        vv[tid] = ev[(size_t)s * KK + tid];
    }
    __syncthreads();
    int d = tid >> 5, o = tid & 31;
    float acc = 0.f;
    #pragma unroll
    for (int k = 0; k < KK; k++)
        acc += sc[k] * vv[k] * m_phi[(k * DD + d) * OO + o];
    g_Fs[s][d][o] = acc;
}

// ---------------- kernel 8: exact recompute of y for t < TFIX ----------------
__global__ void k_fix(const float* __restrict__ inp,
                      const float* __restrict__ m_u,
                      const float* __restrict__ m_y,
                      float* __restrict__ out) {
    __shared__ float u[TFIX * DD];
    __shared__ float Fsh[DD * OO];
    __shared__ float delta[TFIX * OO];
    __shared__ float y1[OO], y2[OO];
    int b = blockIdx.x, tid = threadIdx.x;  // 256
    for (int idx = tid; idx < TFIX * DD; idx += 256)
        u[idx] = inp[(size_t)b * LSEQ * DD + idx];
    __syncthreads();
    float acc[8];
    #pragma unroll
    for (int r = 0; r < 8; r++) {
        int idx = tid + r * 256;
        int t = idx >> 5, o = idx & 31;
        float a = 0.f;
        for (int j = 0; j < 3; j++) {
            if (t >= j) {
                #pragma unroll
                for (int i = 0; i < DD; i++)
                    a += m_u[(o * DD + i) * 3 + j] * u[(t - j) * DD + i];
            }
        }
        acc[r] = a;
    }
    for (int s = 0; s < TFIX; s++) {
        const float* fp = &g_Fs[s][0][0];
        for (int idx = tid; idx < DD * OO; idx += 256) Fsh[idx] = fp[idx];
        __syncthreads();
        #pragma unroll
        for (int r = 0; r < 8; r++) {
            int idx = tid + r * 256;
            int t = idx >> 5, o = idx & 31;
            if (t >= s) {
                float a = acc[r];
                const float* ur = &u[(t - s) * DD];
                #pragma unroll
                for (int d = 0; d < DD; d++)
                    a += ur[d] * Fsh[d * OO + o];
                acc[r] = a;
            }
        }
        __syncthreads();
    }
    #pragma unroll
    for (int r = 0; r < 8; r++) { int idx = tid + r * 256; delta[idx] = acc[r]; }
    __syncthreads();
    if (tid < OO) {
        int o = tid;
        y1[o] = 0.f; y2[o] = 0.f;
        __syncwarp();
        for (int t = 0; t < TFIX; t++) {
            float a = delta[t * OO + o];
            #pragma unroll
            for (int i = 0; i < OO; i++)
                a += m_y[o * 64 + i] * y1[i] + m_y[o * 64 + 32 + i] * y2[i];
            __syncwarp();
            y2[o] = y1[o];
            __syncwarp();
            y1[o] = a;
            __syncwarp();
            out[((size_t)(b * LSEQ + t)) * OO + o] = a;
        }
    }
}

// ---------------- launch ------------------------------------------------------
extern "C" void kernel_launch(void* const* d_in, const int* in_sizes, int n_in,
                              void* d_out, int out_size) {
    const float* inputs  = (const float*)d_in[0];
    const float* eigvals = (const float*)d_in[1];
    const float* eigvecs = (const float*)d_in[2];
    const float* m_u     = (const float*)d_in[3];
    const float* m_phi   = (const float*)d_in[4];
    const float* m_y     = (const float*)d_in[5];
    float* out = (float*)d_out;

    k_tw     <<<4, 1024>>>();
    k_h      <<<1, 1024>>>(m_y);
    k_fft_v  <<<KK / 2, 1024>>>(eigvecs);
    k_W      <<<FH / 2, 1024>>>(eigvals, m_phi, m_u);
    k_fft_fwd<<<BB * DD / 2, 1024>>>(inputs);
    k_mul    <<<FH / 4, 128>>>();
    k_ifft   <<<BB * OO / 2, 1024>>>(out);
    k_Fs     <<<TFIX, 1024>>>(eigvals, eigvecs, m_phi);
    k_fix    <<<BB, 256>>>(inputs, m_u, m_y, out);
}

// round 3
// speedup vs baseline: 1.8934x; 1.5143x over previous
#include <cuda_runtime.h>
#include <math.h>

#define NFFT  4096
#define LOGN  12
#define LSEQ  2048
#define BB    32
#define DD    32
#define KK    32
#define OO    32
#define JH    28      // truncated impulse-response length of y-recurrence
#define FH    2064    // padded half-spectrum bin count (>= 2049, 128B-aligned rows)
#define TFIX  32      // first TFIX timesteps recomputed exactly (alias reaches t<=26)

// ---------------- scratch (device globals; no allocation allowed) ------------
__device__ float2 g_U[BB][DD][FH];     // FFT of inputs      (b, d, f<=half)
__device__ float2 g_G[BB][OO][FH];     // output spectra     (b, o, f<=half)
__device__ float2 g_W[FH][DD][OO];     // combined filter    (f<=half, d, o)
__device__ float2 g_V[KK][FH];         // FFT of eig_vecs    (k, f<=half)
__device__ float  g_h[JH][OO][OO];     // impulse response of recurrence
__device__ float  g_Fs[TFIX][DD][OO];  // time-domain F for the fixup region
__device__ float2 g_tw[NFFT];          // twiddles, per-stage layout [half + p]

// ---------------- helpers ----------------------------------------------------
__device__ __forceinline__ float2 cmulf(float2 a, float2 b) {
    return make_float2(a.x*b.x - a.y*b.y, a.x*b.y + a.y*b.x);
}

// ---------------- kernel 0: twiddle table ------------------------------------
// entries at [half .. 2*half): w_p = exp(-i pi p / half)
__global__ void k_tw() {
    int i = blockIdx.x * 1024 + threadIdx.x;
    if (i >= NFFT) return;
    if (i == 0) { g_tw[0] = make_float2(1.f, 0.f); return; }
    int s = 31 - __clz(i);
    int half = 1 << s;
    int p = i - half;
    float ang = -3.14159265358979323846f * (float)p / (float)half;
    float sn, cs; sincosf(ang, &sn, &cs);
    g_tw[i] = make_float2(cs, sn);
}

// In-place radix-4 DIT FFT over 4096 complex values in shared memory.
// inverse=0 forward (numpy convention), inverse=1 conjugated (scale by caller).
// blockDim.x must be 1024. x must be 16-byte aligned.
__device__ void fft_shared(float2* x, int inverse) {
    int tid = threadIdx.x;
    __syncthreads();
    // base-4 digit-reversal permutation
    for (int i = tid; i < NFFT; i += 1024) {
        unsigned r = __brev((unsigned)i) >> 20;
        r = ((r & 0x555u) << 1) | ((r >> 1) & 0x555u);
        if ((unsigned)i < r) { float2 t = x[i]; x[i] = x[r]; x[r] = t; }
    }
    __syncthreads();
    // stage 0: q=1, twiddles are 1; vectorized float4
    {
        float4* x4 = reinterpret_cast<float4*>(x);
        float4 lo = x4[2 * tid];
        float4 hi = x4[2 * tid + 1];
        float2 A = make_float2(lo.x, lo.y), B = make_float2(lo.z, lo.w);
        float2 C = make_float2(hi.x, hi.y), D = make_float2(hi.z, hi.w);
        float2 t0 = make_float2(A.x + C.x, A.y + C.y);
        float2 t1 = make_float2(A.x - C.x, A.y - C.y);
        float2 t2 = make_float2(B.x + D.x, B.y + D.y);
        float2 t3 = make_float2(B.x - D.x, B.y - D.y);
        float2 y0 = make_float2(t0.x + t2.x, t0.y + t2.y);
        float2 y2 = make_float2(t0.x - t2.x, t0.y - t2.y);
        float2 y1, y3;
        if (!inverse) {
            y1 = make_float2(t1.x + t3.y, t1.y - t3.x);
            y3 = make_float2(t1.x - t3.y, t1.y + t3.x);
        } else {
            y1 = make_float2(t1.x - t3.y, t1.y + t3.x);
            y3 = make_float2(t1.x + t3.y, t1.y - t3.x);
        }
        x4[2 * tid]     = make_float4(y0.x, y0.y, y1.x, y1.y);
        x4[2 * tid + 1] = make_float4(y2.x, y2.y, y3.x, y3.y);
    }
    __syncthreads();
    // stages 1..5
    for (int s = 1; s < 6; s++) {
        int q = 1 << (2 * s);
        int p = tid & (q - 1);
        int g = tid >> (2 * s);
        int base = (g << (2 * s + 2)) + p;
        float2 w1 = __ldg(&g_tw[2 * q + p]);
        float2 w2 = __ldg(&g_tw[q + p]);
        if (inverse) { w1.y = -w1.y; w2.y = -w2.y; }
        float2 w3 = cmulf(w1, w2);
        float2 A = x[base];
        float2 B = cmulf(x[base + q], w1);
        float2 C = cmulf(x[base + 2 * q], w2);
        float2 D = cmulf(x[base + 3 * q], w3);
        float2 t0 = make_float2(A.x + C.x, A.y + C.y);
        float2 t1 = make_float2(A.x - C.x, A.y - C.y);
        float2 t2 = make_float2(B.x + D.x, B.y + D.y);
        float2 t3 = make_float2(B.x - D.x, B.y - D.y);
        x[base]         = make_float2(t0.x + t2.x, t0.y + t2.y);
        x[base + 2 * q] = make_float2(t0.x - t2.x, t0.y - t2.y);
        if (!inverse) {
            x[base + q]     = make_float2(t1.x + t3.y, t1.y - t3.x);
            x[base + 3 * q] = make_float2(t1.x - t3.y, t1.y + t3.x);
        } else {
            x[base + q]     = make_float2(t1.x - t3.y, t1.y + t3.x);
            x[base + 3 * q] = make_float2(t1.x + t3.y, t1.y - t3.x);
        }
        __syncthreads();
    }
}

// ---------------- kernel 1: impulse response of y-recurrence -----------------
__global__ void k_h(const float* __restrict__ m_y) {
    __shared__ float M1[OO * OO], M2[OO * OO], hp[OO * OO], hp2[OO * OO];
    int tid = threadIdx.x;                  // 1024
    int o = tid >> 5, i = tid & 31;
    M1[o * 32 + i] = m_y[o * 64 + i];
    M2[o * 32 + i] = m_y[o * 64 + 32 + i];
    float h0 = (o == i) ? 1.f : 0.f;
    hp2[o * 32 + i] = h0;
    g_h[0][o][i] = h0;
    hp[o * 32 + i] = m_y[o * 64 + i];
    g_h[1][o][i] = m_y[o * 64 + i];
    __syncthreads();
    for (int j = 2; j < JH; j++) {
        float acc = 0.f;
        #pragma unroll
        for (int t = 0; t < 32; t++)
            acc += M1[o * 32 + t] * hp[t * 32 + i] + M2[o * 32 + t] * hp2[t * 32 + i];
        __syncthreads();
        hp2[o * 32 + i] = hp[o * 32 + i];
        __syncthreads();
        hp[o * 32 + i] = acc;
        g_h[j][o][i] = acc;
        __syncthreads();
    }
}

// ---------------- kernel 2: FFT of eig_vecs (pack column pairs) --------------
__global__ void k_fft_v(const float* __restrict__ ev) {
    __shared__ __align__(16) float2 sh[NFFT];
    int kp = blockIdx.x;                    // 0..15 -> filters 2kp, 2kp+1
    int tid = threadIdx.x;                  // 1024
    for (int t = tid; t < LSEQ; t += 1024) {
        const float2 v = *reinterpret_cast<const float2*>(ev + (size_t)t * KK + 2 * kp);
        sh[t] = v;
    }
    for (int t = LSEQ + tid; t < NFFT; t += 1024) sh[t] = make_float2(0.f, 0.f);
    fft_shared(sh, 0);
    for (int f = tid; f < FH; f += 1024) {
        float2 zf = sh[f];
        float2 zm = sh[(NFFT - f) & (NFFT - 1)];
        g_V[2 * kp][f]     = make_float2(0.5f * (zf.x + zm.x), 0.5f * (zf.y - zm.y));
        g_V[2 * kp + 1][f] = make_float2(0.5f * (zf.y + zm.y), 0.5f * (zm.x - zf.x));
    }
}

// ---------------- kernel 3: fused combined filter W (2 bins / block) ---------
__global__ void k_W(const float* __restrict__ eig_vals,
                    const float* __restrict__ m_phi,
                    const float* __restrict__ m_u) {
    __shared__ float2 Hs[2][OO][OO + 1];    // transposed: Hs[bin][o'][o]
    __shared__ float2 FAs[2][DD][OO];
    __shared__ float2 sv[2][KK];
    int f0 = blockIdx.x * 2;
    int tid = threadIdx.x;                  // 1024
    int o = tid >> 5, i = tid & 31;

    float s0, c0, s1, c1;
    sincosf(-6.283185307179586f * (float)f0 / (float)NFFT, &s0, &c0);
    sincosf(-6.283185307179586f * (float)(f0 + 1) / (float)NFFT, &s1, &c1);
    float2 w0 = make_float2(c0, s0), w1 = make_float2(c1, s1);

    float2 acc0 = make_float2(0.f, 0.f), acc1 = acc0;
    float2 cur0 = make_float2(1.f, 0.f), cur1 = cur0;
    #pragma unroll 4
    for (int j = 0; j < JH; j++) {
        float hv = g_h[j][o][i];
        acc0.x += hv * cur0.x; acc0.y += hv * cur0.y;
        acc1.x += hv * cur1.x; acc1.y += hv * cur1.y;
        cur0 = cmulf(cur0, w0);
        cur1 = cmulf(cur1, w1);
    }
    Hs[0][i][o] = acc0;
    Hs[1][i][o] = acc1;

    if (tid < 64) {
        int bin = tid >> 5, k = tid & 31;
        float sc = sqrtf(sqrtf(eig_vals[k]));
        float2 v = g_V[k][f0 + bin];
        sv[bin][k] = make_float2(v.x * sc, v.y * sc);
    }
    __syncthreads();

    int d = o, q = i;
    float2 fa0 = make_float2(0.f, 0.f), fa1 = fa0;
    #pragma unroll 8
    for (int k = 0; k < KK; k++) {
        float m = m_phi[(k * DD + d) * OO + q];
        fa0.x += sv[0][k].x * m; fa0.y += sv[0][k].y * m;
        fa1.x += sv[1][k].x * m; fa1.y += sv[1][k].y * m;
    }
    float a0 = m_u[(q * DD + d) * 3 + 0];
    float a1 = m_u[(q * DD + d) * 3 + 1];
    float a2 = m_u[(q * DD + d) * 3 + 2];
    {
        float c2 = w0.x * w0.x - w0.y * w0.y, sn2 = 2.f * w0.x * w0.y;
        fa0.x += a0 + a1 * w0.x + a2 * c2;
        fa0.y += a1 * w0.y + a2 * sn2;
    }
    {
        float c2 = w1.x * w1.x - w1.y * w1.y, sn2 = 2.f * w1.x * w1.y;
        fa1.x += a0 + a1 * w1.x + a2 * c2;
        fa1.y += a1 * w1.y + a2 * sn2;
    }
    FAs[0][d][q] = fa0;
    FAs[1][d][q] = fa1;
    __syncthreads();

    float2 r0 = make_float2(0.f, 0.f), r1 = r0;
    #pragma unroll 8
    for (int t = 0; t < OO; t++) {
        float2 A = FAs[0][d][t];
        float2 h = Hs[0][t][i];
        r0.x += A.x * h.x - A.y * h.y;
        r0.y += A.x * h.y + A.y * h.x;
        float2 B = FAs[1][d][t];
        float2 g = Hs[1][t][i];
        r1.x += B.x * g.x - B.y * g.y;
        r1.y += B.x * g.y + B.y * g.x;
    }
    g_W[f0][d][i]     = r0;
    g_W[f0 + 1][d][i] = r1;
}

// ---------------- kernel 4: FFT of inputs (pack channel pairs) ---------------
__global__ void k_fft_fwd(const float* __restrict__ inp) {
    __shared__ __align__(16) float2 sh[NFFT];
    int blk = blockIdx.x;                   // 512: (b, dpair)
    int b = blk >> 4, dp = blk & 15;
    int tid = threadIdx.x;                  // 1024
    for (int t = tid; t < LSEQ; t += 1024) {
        const float2 v = *reinterpret_cast<const float2*>(
            inp + ((size_t)(b * LSEQ + t)) * DD + 2 * dp);
        sh[t] = v;
    }
    for (int t = LSEQ + tid; t < NFFT; t += 1024) sh[t] = make_float2(0.f, 0.f);
    fft_shared(sh, 0);
    for (int f = tid; f < FH; f += 1024) {
        float2 zf = sh[f];
        float2 zm = sh[(NFFT - f) & (NFFT - 1)];
        g_U[b][2 * dp][f]     = make_float2(0.5f * (zf.x + zm.x), 0.5f * (zf.y - zm.y));
        g_U[b][2 * dp + 1][f] = make_float2(0.5f * (zf.y + zm.y), 0.5f * (zm.x - zf.x));
    }
}

// ---------------- kernel 5: per-bin complex matvec G = U * W -----------------
// 256 threads = (bh:2, o:32, fi:4). W column in regs (reused over 32 batches),
// U staged in padded shared, broadcast float4 reads.
__global__ void k_mul() {
    __shared__ __align__(16) float2 Us[BB][4][DD + 2];   // ~34.8 KB, fi-stride pad
    int tid = threadIdx.x;            // 256
    int f0 = blockIdx.x * 4;
    #pragma unroll
    for (int k = 0; k < 4; k++) {
        int pair = tid + k * 256;     // pair = b*32 + d
        int b = pair >> 5, d = pair & 31;
        const float4* src = reinterpret_cast<const float4*>(&g_U[b][d][f0]);
        float4 v0 = src[0], v1 = src[1];
        Us[b][0][d] = make_float2(v0.x, v0.y);
        Us[b][1][d] = make_float2(v0.z, v0.w);
        Us[b][2][d] = make_float2(v1.x, v1.y);
        Us[b][3][d] = make_float2(v1.z, v1.w);
    }
    int bh = tid >> 7;
    int o  = (tid >> 2) & 31;
    int fi = tid & 3;
    int f  = f0 + fi;
    float2 Wreg[DD];
    #pragma unroll
    for (int d = 0; d < DD; d++) Wreg[d] = g_W[f][d][o];
    __syncthreads();
    for (int bi = 0; bi < 16; bi++) {
        int b = bh * 16 + bi;
        float2 a0 = make_float2(0.f, 0.f), a1 = a0;
        const float4* up = reinterpret_cast<const float4*>(&Us[b][fi][0]);
        #pragma unroll
        for (int d2 = 0; d2 < DD / 2; d2++) {
            float4 uv = up[d2];
            float2 w0 = Wreg[2 * d2], w1 = Wreg[2 * d2 + 1];
            a0.x += uv.x * w0.x - uv.y * w0.y;
            a0.y += uv.x * w0.y + uv.y * w0.x;
            a1.x += uv.z * w1.x - uv.w * w1.y;
            a1.y += uv.z * w1.y + uv.w * w1.x;
        }
        g_G[b][o][f] = make_float2(a0.x + a1.x, a0.y + a1.y);
    }
}

// ---------------- kernel 6: inverse FFT (Hermitian reconstruct + pack) -------
__global__ void k_ifft(float* __restrict__ out) {
    __shared__ __align__(16) float2 sh[NFFT];
    int blk = blockIdx.x;                   // 512: (b, opair)
    int b = blk >> 4, op = blk & 15;
    int tid = threadIdx.x;                  // 1024
    for (int f = tid; f < NFFT; f += 1024) {
        int mir = f > NFFT / 2;
        int fm = mir ? NFFT - f : f;
        float sgn = mir ? -1.f : 1.f;
        float2 a = g_G[b][2 * op][fm];
        float2 c = g_G[b][2 * op + 1][fm];
        a.y *= sgn; c.y *= sgn;
        sh[f] = make_float2(a.x - c.y, a.y + c.x);
    }
    fft_shared(sh, 1);
    const float inv = 1.f / (float)NFFT;
    for (int t = tid; t < LSEQ; t += 1024) {
        float2 z = sh[t];
        float2* p = reinterpret_cast<float2*>(out + ((size_t)(b * LSEQ + t)) * OO + 2 * op);
        *p = make_float2(z.x * inv, z.y * inv);
    }
}

// ---------------- kernel 7: time-domain F for the fixup region ---------------
__global__ void k_Fs(const float* __restrict__ eig_vals,
                     const float* __restrict__ ev,
                     const float* __restrict__ m_phi) {
    __shared__ float sc[KK];
    __shared__ float vv[KK];
    int s = blockIdx.x;                     // 0..TFIX-1
    int tid = threadIdx.x;                  // 1024
    if (tid < KK) {
        sc[tid] = sqrtf(sqrtf(eig_vals[tid]));
        vv[tid] = ev[(size_t)s * KK + tid];
    }
    __syncthreads();
    int d = tid >> 5, o = tid & 31;
    float acc = 0.f;
    #pragma unroll
    for (int k = 0; k < KK; k++)
        acc += sc[k] * vv[k] * m_phi[(k * DD + d) * OO + o];
    g_Fs[s][d][o] = acc;
}

// ---------------- kernel 8: exact recompute of y for t < TFIX ----------------
__global__ void k_fix(const float* __restrict__ inp,
                      const float* __restrict__ m_u,
                      const float* __restrict__ m_y,
                      float* __restrict__ out) {
    __shared__ float u[TFIX * DD];
    __shared__ float Fsh[DD * OO];
    __shared__ float delta[TFIX * OO];
    __shared__ float y1[OO], y2[OO];
    int b = blockIdx.x, tid = threadIdx.x;  // 256
    for (int idx = tid; idx < TFIX * DD; idx += 256)
        u[idx] = inp[(size_t)b * LSEQ * DD + idx];
    __syncthreads();
    float acc[4];
    #pragma unroll
    for (int r = 0; r < 4; r++) {
        int idx = tid + r * 256;
        int t = idx >> 5, o = idx & 31;
        float a = 0.f;
        for (int j = 0; j < 3; j++) {
            if (t >= j) {
                #pragma unroll
                for (int i = 0; i < DD; i++)
                    a += m_u[(o * DD + i) * 3 + j] * u[(t - j) * DD + i];
            }
        }
        acc[r] = a;
    }
    for (int s = 0; s < TFIX; s++) {
        const float* fp = &g_Fs[s][0][0];
        for (int idx = tid; idx < DD * OO; idx += 256) Fsh[idx] = fp[idx];
        __syncthreads();
        #pragma unroll
        for (int r = 0; r < 4; r++) {
            int idx = tid + r * 256;
            int t = idx >> 5, o = idx & 31;
            if (t >= s) {
                float a = acc[r];
                const float* ur = &u[(t - s) * DD];
                #pragma unroll
                for (int d = 0; d < DD; d++)
                    a += ur[d] * Fsh[d * OO + o];
                acc[r] = a;
            }
        }
        __syncthreads();
    }
    #pragma unroll
    for (int r = 0; r < 4; r++) { int idx = tid + r * 256; delta[idx] = acc[r]; }
    __syncthreads();
    if (tid < OO) {
        int o = tid;
        y1[o] = 0.f; y2[o] = 0.f;
        __syncwarp();
        for (int t = 0; t < TFIX; t++) {
            float a = delta[t * OO + o];
            #pragma unroll
            for (int i = 0; i < OO; i++)
                a += m_y[o * 64 + i] * y1[i] + m_y[o * 64 + 32 + i] * y2[i];
            __syncwarp();
            y2[o] = y1[o];
            __syncwarp();
            y1[o] = a;
            __syncwarp();
            out[((size_t)(b * LSEQ + t)) * OO + o] = a;
        }
    }
}

// ---------------- launch ------------------------------------------------------
extern "C" void kernel_launch(void* const* d_in, const int* in_sizes, int n_in,
                              void* d_out, int out_size) {
    const float* inputs  = (const float*)d_in[0];
    const float* eigvals = (const float*)d_in[1];
    const float* eigvecs = (const float*)d_in[2];
    const float* m_u     = (const float*)d_in[3];
    const float* m_phi   = (const float*)d_in[4];
    const float* m_y     = (const float*)d_in[5];
    float* out = (float*)d_out;

    k_tw     <<<4, 1024>>>();
    k_h      <<<1, 1024>>>(m_y);
    k_fft_v  <<<KK / 2, 1024>>>(eigvecs);
    k_W      <<<FH / 2, 1024>>>(eigvals, m_phi, m_u);
    k_fft_fwd<<<BB * DD / 2, 1024>>>(inputs);
    k_mul    <<<FH / 4, 256>>>();
    k_ifft   <<<BB * OO / 2, 1024>>>(out);
    k_Fs     <<<TFIX, 1024>>>(eigvals, eigvecs, m_phi);
    k_fix    <<<BB, 256>>>(inputs, m_u, m_y, out);
}